// round 5
// baseline (speedup 1.0000x reference)
#include <cuda_runtime.h>
#include <math.h>

// ---------------------------------------------------------------------------
// TGAT fused kernel, restructured:
//   te0      = time2vec(0)                         (const)
//   qc       = te0 @ Wq'        Wq' = Wq[128:192]
//   Wqk      = Wq128 @ Wk'^T                        [128,64]
//   qkc      = qc @ Wk'^T                           [64]
//   WvO128   = Wv128 @ Wo                           [128,128]
//   Wvo      = Wv' @ Wo                             [64,128]
//   scratch  = x @ [Wq128 | Wk128 | WvO128 | Wqk] + [qc|0|0|qkc]   (N x 448)
//              = [ Q | XK | XVO | QKp ]
//   score_nk = (Q[n]·XK[j] + QKp[n]·te(t)) / sqrt(128)
//   out[n]   = relu( sum_k attn_k * XVO[j_k] + tebar @ Wvo + bo ),
//              tebar = sum_k attn_k * te_k
// ---------------------------------------------------------------------------

#define MAXN 50176
#define FEAT 128
#define T2V  64
#define KNBR 16
#define NCOL 448   // 128 Q + 128 XK + 128 XVO + 64 QKp

__device__ __align__(16) float g_scr[MAXN * NCOL];     // ~90 MB scratch
__device__ __align__(16) float g_Wcomb[FEAT * NCOL];   // combined GEMM weights
__device__ __align__(16) float g_bias[NCOL];
__device__ __align__(16) float g_Wvo[T2V * FEAT];      // Wv' @ Wo

// ---------------------------------------------------------------------------
// Kernel 0: fold weights. One thread per output element. Tiny.
// ---------------------------------------------------------------------------
__global__ void precompute_kernel(const float* __restrict__ Wq,
                                  const float* __restrict__ Wk,
                                  const float* __restrict__ Wv,
                                  const float* __restrict__ Wo,
                                  const float* __restrict__ b0p,
                                  const float* __restrict__ Bt) {
    int e = blockIdx.x * blockDim.x + threadIdx.x;
    const int NW = FEAT * NCOL;              // 57344
    if (e < NW) {
        int f = e / NCOL, c = e % NCOL;
        float v;
        if (c < 128) {
            v = Wq[f * 128 + c];
        } else if (c < 256) {
            v = Wk[f * 128 + (c - 128)];
        } else if (c < 384) {
            int cc = c - 256;
            float s = 0.f;
            #pragma unroll 8
            for (int h = 0; h < 128; h++) s += Wv[f * 128 + h] * Wo[h * 128 + cc];
            v = s;
        } else {
            int j = c - 384;
            float s = 0.f;
            #pragma unroll 8
            for (int h = 0; h < 128; h++) s += Wq[f * 128 + h] * Wk[(128 + j) * 128 + h];
            v = s;
        }
        g_Wcomb[e] = v;
    } else if (e < NW + NCOL) {
        int c = e - NW;
        float v = 0.f;
        if (c < 128) {
            // qc[c] = sum_f te0[f] * Wq[(128+f)*128 + c]
            float s = b0p[0] * Wq[128 * 128 + c];
            for (int f = 1; f < T2V; f++)
                s += sinf(Bt[f - 1]) * Wq[(128 + f) * 128 + c];
            v = s;
        } else if (c >= 384) {
            int j = c - 384;
            // qkc[j] = sum_h qc[h] * Wk[(128+j)*128 + h]
            float te0[T2V];
            te0[0] = b0p[0];
            for (int f = 1; f < T2V; f++) te0[f] = sinf(Bt[f - 1]);
            float s = 0.f;
            for (int h = 0; h < 128; h++) {
                float qc = 0.f;
                #pragma unroll 8
                for (int f = 0; f < T2V; f++) qc += te0[f] * Wq[(128 + f) * 128 + h];
                s += qc * Wk[(128 + j) * 128 + h];
            }
            v = s;
        }
        g_bias[c] = v;
    } else if (e < NW + NCOL + T2V * FEAT) {
        int r = e - (NW + NCOL);
        int j = r / 128, c = r % 128;
        float s = 0.f;
        #pragma unroll 8
        for (int h = 0; h < 128; h++) s += Wv[(128 + j) * 128 + h] * Wo[h * 128 + c];
        g_Wvo[r] = s;
    }
}

// ---------------------------------------------------------------------------
// Kernel 1: fp32 SGEMM  scr[N,448] = x[N,128] @ Wcomb[128,448] + bias
// Tiles: BM=128, BN=64, BK=32, 256 threads, 8x4 microtile per thread.
// ---------------------------------------------------------------------------
#define BM 128
#define BN 64
#define BK 32

__global__ void __launch_bounds__(256) gemm_kernel(const float* __restrict__ x, int N) {
    __shared__ float As[BK][BM + 4];   // A transposed, padded
    __shared__ float Bs[BK][BN];

    int tid = threadIdx.x;
    int tx = tid & 15;   // N direction (16 * 4 = 64)
    int ty = tid >> 4;   // M direction (16 * 8 = 128)
    int row0 = blockIdx.x * BM;
    int c0   = blockIdx.y * BN;

    float acc[8][4];
    #pragma unroll
    for (int i = 0; i < 8; i++)
        #pragma unroll
        for (int j = 0; j < 4; j++) acc[i][j] = 0.f;

    for (int kk = 0; kk < FEAT; kk += BK) {
        // Load A tile (128x32) with transpose: 4 float4 / thread
        #pragma unroll
        for (int i = 0; i < 4; i++) {
            int slot = tid + i * 256;
            int m  = slot >> 3;
            int k4 = (slot & 7) << 2;
            int r  = row0 + m;
            float4 a = (r < N) ? *(const float4*)(x + (size_t)r * FEAT + kk + k4)
                               : make_float4(0.f, 0.f, 0.f, 0.f);
            As[k4 + 0][m] = a.x;
            As[k4 + 1][m] = a.y;
            As[k4 + 2][m] = a.z;
            As[k4 + 3][m] = a.w;
        }
        // Load B tile (32x64): 2 float4 / thread
        #pragma unroll
        for (int i = 0; i < 2; i++) {
            int slot = tid + i * 256;
            int k  = slot >> 4;
            int c4 = (slot & 15) << 2;
            *(float4*)(&Bs[k][c4]) = *(const float4*)(g_Wcomb + (size_t)(kk + k) * NCOL + c0 + c4);
        }
        __syncthreads();

        #pragma unroll
        for (int k = 0; k < BK; k++) {
            float af[8], bf[4];
            *(float4*)(af)     = *(const float4*)(&As[k][ty * 8]);
            *(float4*)(af + 4) = *(const float4*)(&As[k][ty * 8 + 4]);
            *(float4*)(bf)     = *(const float4*)(&Bs[k][tx * 4]);
            #pragma unroll
            for (int i = 0; i < 8; i++)
                #pragma unroll
                for (int j = 0; j < 4; j++)
                    acc[i][j] = fmaf(af[i], bf[j], acc[i][j]);
        }
        __syncthreads();
    }

    float4 bias = *(const float4*)(g_bias + c0 + tx * 4);
    #pragma unroll
    for (int i = 0; i < 8; i++) {
        int r = row0 + ty * 8 + i;
        if (r < N) {
            float4 o;
            o.x = acc[i][0] + bias.x;
            o.y = acc[i][1] + bias.y;
            o.z = acc[i][2] + bias.z;
            o.w = acc[i][3] + bias.w;
            *(float4*)(g_scr + (size_t)r * NCOL + c0 + tx * 4) = o;
        }
    }
}

// ---------------------------------------------------------------------------
// Kernel 2: fused attention. One warp per node, 8 warps (256 thr) per block.
// ---------------------------------------------------------------------------
__global__ void __launch_bounds__(256) attn_kernel(
    const float* __restrict__ ts, const int* __restrict__ idx,
    const float* __restrict__ w0p, const float* __restrict__ b0p,
    const float* __restrict__ Wt,  const float* __restrict__ Bt,
    const float* __restrict__ bo,  float* __restrict__ out, int N) {

    __shared__ float te_s[8][KNBR * T2V];   // 32 KB

    const float* __restrict__ scr = g_scr;
    const float* __restrict__ wvo = g_Wvo;

    int warp = threadIdx.x >> 5;
    int lane = threadIdx.x & 31;
    int n = blockIdx.x * 8 + warp;
    if (n >= N) return;

    const float* scr_n = scr + (size_t)n * NCOL;
    float4 qv   = *(const float4*)(scr_n + lane * 4);
    float  qkp0 = scr_n[384 + lane];
    float  qkp1 = scr_n[384 + 32 + lane];

    float w0 = w0p[0], b0 = b0p[0];
    float W0 = (lane == 0) ? 0.f : Wt[lane - 1];
    float B0 = (lane == 0) ? 0.f : Bt[lane - 1];
    float W1 = Wt[lane + 31];
    float B1 = Bt[lane + 31];

    float* mte = te_s[warp];
    int   jj[KNBR];
    float s[KNBR];

    // Pass 1: te + scores
    #pragma unroll
    for (int k = 0; k < KNBR; k++) {
        float t = ts[(size_t)n * KNBR + k];
        int   j = idx[(size_t)n * KNBR + k];
        jj[k] = j;
        float v0 = (lane == 0) ? fmaf(t, w0, b0) : sinf(fmaf(t, W0, B0));
        float v1 = sinf(fmaf(t, W1, B1));
        mte[k * T2V + lane]      = v0;
        mte[k * T2V + 32 + lane] = v1;
        float4 kv = *(const float4*)(scr + (size_t)j * NCOL + 128 + lane * 4);
        float p = qv.x * kv.x + qv.y * kv.y + qv.z * kv.z + qv.w * kv.w
                + qkp0 * v0 + qkp1 * v1;
        #pragma unroll
        for (int off = 16; off; off >>= 1)
            p += __shfl_xor_sync(0xffffffffu, p, off);
        s[k] = p * 0.08838834764831845f;   // 1/sqrt(128)
    }

    // Softmax over 16 scores (replicated in every lane)
    float m = s[0];
    #pragma unroll
    for (int k = 1; k < KNBR; k++) m = fmaxf(m, s[k]);
    float wsum = 0.f;
    #pragma unroll
    for (int k = 0; k < KNBR; k++) { s[k] = __expf(s[k] - m); wsum += s[k]; }
    float inv = 1.f / wsum;

    // Pass 2: tebar + weighted XVO gather
    float4 acc = make_float4(0.f, 0.f, 0.f, 0.f);
    float tb0 = 0.f, tb1 = 0.f;
    #pragma unroll
    for (int k = 0; k < KNBR; k++) {
        float a = s[k] * inv;
        tb0 = fmaf(a, mte[k * T2V + lane], tb0);
        tb1 = fmaf(a, mte[k * T2V + 32 + lane], tb1);
        float4 vv = *(const float4*)(scr + (size_t)jj[k] * NCOL + 256 + lane * 4);
        acc.x = fmaf(a, vv.x, acc.x);
        acc.y = fmaf(a, vv.y, acc.y);
        acc.z = fmaf(a, vv.z, acc.z);
        acc.w = fmaf(a, vv.w, acc.w);
    }

    // Broadcast tebar through smem (reuse row 0 of this warp's te buffer)
    __syncwarp();
    mte[lane]      = tb0;
    mte[32 + lane] = tb1;
    __syncwarp();

    // acc += tebar @ Wvo  (Wvo is 32 KB -> L1-resident)
    const float4* Wvo4 = (const float4*)wvo;
    #pragma unroll 8
    for (int f = 0; f < T2V; f++) {
        float tb = mte[f];
        float4 wv = __ldg(&Wvo4[f * 32 + lane]);
        acc.x = fmaf(tb, wv.x, acc.x);
        acc.y = fmaf(tb, wv.y, acc.y);
        acc.z = fmaf(tb, wv.z, acc.z);
        acc.w = fmaf(tb, wv.w, acc.w);
    }

    float4 bo4 = *(const float4*)(bo + lane * 4);
    float4 o;
    o.x = fmaxf(acc.x + bo4.x, 0.f);
    o.y = fmaxf(acc.y + bo4.y, 0.f);
    o.z = fmaxf(acc.z + bo4.z, 0.f);
    o.w = fmaxf(acc.w + bo4.w, 0.f);
    *(float4*)(out + (size_t)n * FEAT + lane * 4) = o;
}

// ---------------------------------------------------------------------------
extern "C" void kernel_launch(void* const* d_in, const int* in_sizes, int n_in,
                              void* d_out, int out_size) {
    const float* x    = (const float*)d_in[0];
    const float* ts   = (const float*)d_in[1];
    const int*   idx  = (const int*)  d_in[2];
    const float* w0p  = (const float*)d_in[3];
    const float* b0p  = (const float*)d_in[4];
    const float* Wt   = (const float*)d_in[5];
    const float* Bt   = (const float*)d_in[6];
    const float* Wq   = (const float*)d_in[7];
    const float* Wk   = (const float*)d_in[8];
    const float* Wv   = (const float*)d_in[9];
    const float* Wo   = (const float*)d_in[10];
    const float* bo   = (const float*)d_in[11];
    float* out = (float*)d_out;

    int N = in_sizes[0] / FEAT;
    if (N > MAXN) N = MAXN;

    // Kernel 0: weight folding (66 K tasks)
    {
        int tasks = FEAT * NCOL + NCOL + T2V * FEAT;
        int blocks = (tasks + 255) / 256;
        precompute_kernel<<<blocks, 256>>>(Wq, Wk, Wv, Wo, b0p, Bt);
    }
    // Kernel 1: x @ Wcomb + bias  ->  g_scr
    {
        dim3 grid((N + BM - 1) / BM, NCOL / BN);
        gemm_kernel<<<grid, 256>>>(x, N);
    }
    // Kernel 2: fused attention
    {
        int blocks = (N + 7) / 8;
        attn_kernel<<<blocks, 256>>>(ts, idx, w0p, b0p, Wt, Bt, bo, out, N);
    }
}

// round 7
// speedup vs baseline: 1.0958x; 1.0958x over previous
#include <cuda_runtime.h>
#include <math.h>

// ---------------------------------------------------------------------------
// TGAT fused kernel, restructured:
//   scratch  = x @ [Wq128 | Wk128 | Wv128@Wo | Wq128@Wk'^T] + [qc|0|0|qkc]
//            = [ Q | XK | XVO | QKp ]   (N x 448)
//   score_nk = (Q[n]·XK[j] + QKp[n]·te(t)) / sqrt(128)
//   out[n]   = relu( sum_k attn_k * XVO[j_k] + tebar @ (Wv'@Wo) + bo )
// ---------------------------------------------------------------------------

#define MAXN 50176
#define FEAT 128
#define T2V  64
#define KNBR 16
#define NCOL 448   // 128 Q + 128 XK + 128 XVO + 64 QKp

__device__ __align__(16) float g_scr[MAXN * NCOL];     // ~90 MB scratch
__device__ __align__(16) float g_Wcomb[FEAT * NCOL];   // combined GEMM weights
__device__ __align__(16) float g_bias[NCOL];
__device__ __align__(16) float g_Wvo[T2V * FEAT];      // Wv' @ Wo

// ---------------------------------------------------------------------------
// Kernel 0a: fold weights, warp-parallel & coalesced.
// Warp task map:
//   [0, 512)          : WvO128[f][cg*32+lane]  = sum_h Wv[f][h]*Wo[h][c]
//   [512, 768)        : Wvo[j][cg*32+lane]     = sum_h Wv[128+j][h]*Wo[h][c]
//   [768, 768+8192)   : Wqk[f][j] (warp-reduce over h) + Wq/Wk column copy
//   [8960, 8964)      : qc[cg*32+lane]         = sum_f te0[f]*Wq[128+f][c]
//   [8964, 8972)      : zero-fill bias cols [128,384)
// ---------------------------------------------------------------------------
__global__ void __launch_bounds__(256) precompute_a(
        const float* __restrict__ Wq, const float* __restrict__ Wk,
        const float* __restrict__ Wv, const float* __restrict__ Wo,
        const float* __restrict__ b0p, const float* __restrict__ Bt) {
    int w    = (blockIdx.x * blockDim.x + threadIdx.x) >> 5;
    int lane = threadIdx.x & 31;

    if (w < 512) {                         // WvO128 [128 x 128]
        int f = w >> 2, c = ((w & 3) << 5) + lane;
        float acc = 0.f;
        #pragma unroll 8
        for (int h = 0; h < 128; h++)
            acc = fmaf(Wv[f * 128 + h], Wo[h * 128 + c], acc);
        g_Wcomb[f * NCOL + 256 + c] = acc;
    } else if (w < 768) {                  // Wvo [64 x 128]
        int j = (w - 512) >> 2, c = ((w & 3) << 5) + lane;
        float acc = 0.f;
        #pragma unroll 8
        for (int h = 0; h < 128; h++)
            acc = fmaf(Wv[(128 + j) * 128 + h], Wo[h * 128 + c], acc);
        g_Wvo[j * 128 + c] = acc;
    } else if (w < 768 + 8192) {           // Wqk [128 x 64] + copy Wq/Wk cols
        int e = w - 768;
        int f = e >> 6, j = e & 63;
        float acc = 0.f;
        #pragma unroll
        for (int i = 0; i < 4; i++) {
            int h = lane + i * 32;
            acc = fmaf(Wq[f * 128 + h], Wk[(128 + j) * 128 + h], acc);
        }
        #pragma unroll
        for (int off = 16; off; off >>= 1)
            acc += __shfl_xor_sync(0xffffffffu, acc, off);
        if (lane == 0) g_Wcomb[f * NCOL + 384 + j] = acc;
        // Copy plain Wq/Wk columns: c = j*2+lane spans [0,128) exactly
        // (64 j-values x 2 lanes). NO other writes to Q/XK blocks.
        if (lane < 2) {
            int c = j * 2 + lane;
            g_Wcomb[f * NCOL + c]       = Wq[f * 128 + c];
            g_Wcomb[f * NCOL + 128 + c] = Wk[f * 128 + c];
        }
    } else if (w < 8964) {                 // qc [128]
        int c = ((w - 8960) << 5) + lane;
        float acc = b0p[0] * Wq[128 * 128 + c];
        for (int f = 1; f < T2V; f++)
            acc = fmaf(sinf(Bt[f - 1]), Wq[(128 + f) * 128 + c], acc);
        g_bias[c] = acc;
    } else if (w < 8972) {                 // zero bias cols [128,384)
        int c = 128 + ((w - 8964) << 5) + lane;
        g_bias[c] = 0.f;
    }
}

// ---------------------------------------------------------------------------
// Kernel 0b: qkc[j] = sum_h qc[h] * Wk[128+j][h]  (needs qc from 0a)
// ---------------------------------------------------------------------------
__global__ void precompute_b(const float* __restrict__ Wk) {
    int w    = (blockIdx.x * blockDim.x + threadIdx.x) >> 5;
    int lane = threadIdx.x & 31;
    if (w >= 64) return;
    float acc = 0.f;
    #pragma unroll
    for (int i = 0; i < 4; i++) {
        int h = lane + i * 32;
        acc = fmaf(g_bias[h], Wk[(128 + w) * 128 + h], acc);
    }
    #pragma unroll
    for (int off = 16; off; off >>= 1)
        acc += __shfl_xor_sync(0xffffffffu, acc, off);
    if (lane == 0) g_bias[384 + w] = acc;
}

// ---------------------------------------------------------------------------
// Kernel 1: fp32 SGEMM  scr[N,448] = x[N,128] @ Wcomb[128,448] + bias
// BM=128, BN=64, BK=32, 128 threads, 8x8 microtile (1 B/FMA: smem balanced).
// ---------------------------------------------------------------------------
#define BM 128
#define BN 64
#define BK 32

__global__ void __launch_bounds__(128) gemm_kernel(const float* __restrict__ x, int N) {
    __shared__ float As[BK][BM + 4];   // A transposed, padded
    __shared__ float Bs[BK][BN];

    int tid = threadIdx.x;
    int tx = tid & 7;    // N direction (8 * 8 = 64)
    int ty = tid >> 3;   // M direction (16 * 8 = 128)
    int row0 = blockIdx.x * BM;
    int c0   = blockIdx.y * BN;

    float acc[8][8];
    #pragma unroll
    for (int i = 0; i < 8; i++)
        #pragma unroll
        for (int j = 0; j < 8; j++) acc[i][j] = 0.f;

    for (int kk = 0; kk < FEAT; kk += BK) {
        // Load A tile (128x32) with transpose: 8 float4 / thread
        #pragma unroll
        for (int i = 0; i < 8; i++) {
            int slot = tid + i * 128;
            int m  = slot >> 3;
            int k4 = (slot & 7) << 2;
            int r  = row0 + m;
            float4 a = (r < N) ? *(const float4*)(x + (size_t)r * FEAT + kk + k4)
                               : make_float4(0.f, 0.f, 0.f, 0.f);
            As[k4 + 0][m] = a.x;
            As[k4 + 1][m] = a.y;
            As[k4 + 2][m] = a.z;
            As[k4 + 3][m] = a.w;
        }
        // Load B tile (32x64): 4 float4 / thread
        #pragma unroll
        for (int i = 0; i < 4; i++) {
            int slot = tid + i * 128;
            int k  = slot >> 4;
            int c4 = (slot & 15) << 2;
            *(float4*)(&Bs[k][c4]) = *(const float4*)(g_Wcomb + (size_t)(kk + k) * NCOL + c0 + c4);
        }
        __syncthreads();

        #pragma unroll
        for (int k = 0; k < BK; k++) {
            float af[8], bf[8];
            *(float4*)(af)     = *(const float4*)(&As[k][ty * 8]);
            *(float4*)(af + 4) = *(const float4*)(&As[k][ty * 8 + 4]);
            *(float4*)(bf)     = *(const float4*)(&Bs[k][tx * 8]);
            *(float4*)(bf + 4) = *(const float4*)(&Bs[k][tx * 8 + 4]);
            #pragma unroll
            for (int i = 0; i < 8; i++)
                #pragma unroll
                for (int j = 0; j < 8; j++)
                    acc[i][j] = fmaf(af[i], bf[j], acc[i][j]);
        }
        __syncthreads();
    }

    float4 bias0 = *(const float4*)(g_bias + c0 + tx * 8);
    float4 bias1 = *(const float4*)(g_bias + c0 + tx * 8 + 4);
    #pragma unroll
    for (int i = 0; i < 8; i++) {
        int r = row0 + ty * 8 + i;
        if (r < N) {
            float4 o0, o1;
            o0.x = acc[i][0] + bias0.x;  o0.y = acc[i][1] + bias0.y;
            o0.z = acc[i][2] + bias0.z;  o0.w = acc[i][3] + bias0.w;
            o1.x = acc[i][4] + bias1.x;  o1.y = acc[i][5] + bias1.y;
            o1.z = acc[i][6] + bias1.z;  o1.w = acc[i][7] + bias1.w;
            *(float4*)(g_scr + (size_t)r * NCOL + c0 + tx * 8)     = o0;
            *(float4*)(g_scr + (size_t)r * NCOL + c0 + tx * 8 + 4) = o1;
        }
    }
}

// ---------------------------------------------------------------------------
// Kernel 2: fused attention. One warp per node, 8 warps (256 thr) per block.
// ---------------------------------------------------------------------------
__global__ void __launch_bounds__(256) attn_kernel(
    const float* __restrict__ ts, const int* __restrict__ idx,
    const float* __restrict__ w0p, const float* __restrict__ b0p,
    const float* __restrict__ Wt,  const float* __restrict__ Bt,
    const float* __restrict__ bo,  float* __restrict__ out, int N) {

    __shared__ float te_s[8][KNBR * T2V];   // 32 KB

    const float* __restrict__ scr = g_scr;
    const float* __restrict__ wvo = g_Wvo;

    int warp = threadIdx.x >> 5;
    int lane = threadIdx.x & 31;
    int n = blockIdx.x * 8 + warp;
    if (n >= N) return;

    const float* scr_n = scr + (size_t)n * NCOL;
    float4 qv   = *(const float4*)(scr_n + lane * 4);
    float  qkp0 = scr_n[384 + lane];
    float  qkp1 = scr_n[384 + 32 + lane];

    float w0 = w0p[0], b0 = b0p[0];
    float W0 = (lane == 0) ? 0.f : Wt[lane - 1];
    float B0 = (lane == 0) ? 0.f : Bt[lane - 1];
    float W1 = Wt[lane + 31];
    float B1 = Bt[lane + 31];

    float* mte = te_s[warp];
    int   jj[KNBR];
    float s[KNBR];

    // Pass 1: te + scores
    #pragma unroll
    for (int k = 0; k < KNBR; k++) {
        float t = ts[(size_t)n * KNBR + k];
        int   j = idx[(size_t)n * KNBR + k];
        jj[k] = j;
        float v0 = (lane == 0) ? fmaf(t, w0, b0) : sinf(fmaf(t, W0, B0));
        float v1 = sinf(fmaf(t, W1, B1));
        mte[k * T2V + lane]      = v0;
        mte[k * T2V + 32 + lane] = v1;
        float4 kv = *(const float4*)(scr + (size_t)j * NCOL + 128 + lane * 4);
        float p = qv.x * kv.x + qv.y * kv.y + qv.z * kv.z + qv.w * kv.w
                + qkp0 * v0 + qkp1 * v1;
        #pragma unroll
        for (int off = 16; off; off >>= 1)
            p += __shfl_xor_sync(0xffffffffu, p, off);
        s[k] = p * 0.08838834764831845f;   // 1/sqrt(128)
    }

    // Softmax over 16 scores (replicated in every lane)
    float m = s[0];
    #pragma unroll
    for (int k = 1; k < KNBR; k++) m = fmaxf(m, s[k]);
    float wsum = 0.f;
    #pragma unroll
    for (int k = 0; k < KNBR; k++) { s[k] = __expf(s[k] - m); wsum += s[k]; }
    float inv = 1.f / wsum;

    // Pass 2: tebar + weighted XVO gather
    float4 acc = make_float4(0.f, 0.f, 0.f, 0.f);
    float tb0 = 0.f, tb1 = 0.f;
    #pragma unroll
    for (int k = 0; k < KNBR; k++) {
        float a = s[k] * inv;
        tb0 = fmaf(a, mte[k * T2V + lane], tb0);
        tb1 = fmaf(a, mte[k * T2V + 32 + lane], tb1);
        float4 vv = *(const float4*)(scr + (size_t)jj[k] * NCOL + 256 + lane * 4);
        acc.x = fmaf(a, vv.x, acc.x);
        acc.y = fmaf(a, vv.y, acc.y);
        acc.z = fmaf(a, vv.z, acc.z);
        acc.w = fmaf(a, vv.w, acc.w);
    }

    // Broadcast tebar through smem (reuse row 0 of this warp's te buffer)
    __syncwarp();
    mte[lane]      = tb0;
    mte[32 + lane] = tb1;
    __syncwarp();

    // acc += tebar @ Wvo  (Wvo is 32 KB -> L1/L2-resident)
    const float4* Wvo4 = (const float4*)wvo;
    #pragma unroll 8
    for (int f = 0; f < T2V; f++) {
        float tb = mte[f];
        float4 wv = __ldg(&Wvo4[f * 32 + lane]);
        acc.x = fmaf(tb, wv.x, acc.x);
        acc.y = fmaf(tb, wv.y, acc.y);
        acc.z = fmaf(tb, wv.z, acc.z);
        acc.w = fmaf(tb, wv.w, acc.w);
    }

    float4 bo4 = *(const float4*)(bo + lane * 4);
    float4 o;
    o.x = fmaxf(acc.x + bo4.x, 0.f);
    o.y = fmaxf(acc.y + bo4.y, 0.f);
    o.z = fmaxf(acc.z + bo4.z, 0.f);
    o.w = fmaxf(acc.w + bo4.w, 0.f);
    *(float4*)(out + (size_t)n * FEAT + lane * 4) = o;
}

// ---------------------------------------------------------------------------
extern "C" void kernel_launch(void* const* d_in, const int* in_sizes, int n_in,
                              void* d_out, int out_size) {
    const float* x    = (const float*)d_in[0];
    const float* ts   = (const float*)d_in[1];
    const int*   idx  = (const int*)  d_in[2];
    const float* w0p  = (const float*)d_in[3];
    const float* b0p  = (const float*)d_in[4];
    const float* Wt   = (const float*)d_in[5];
    const float* Bt   = (const float*)d_in[6];
    const float* Wq   = (const float*)d_in[7];
    const float* Wk   = (const float*)d_in[8];
    const float* Wv   = (const float*)d_in[9];
    const float* Wo   = (const float*)d_in[10];
    const float* bo   = (const float*)d_in[11];
    float* out = (float*)d_out;

    int N = in_sizes[0] / FEAT;
    if (N > MAXN) N = MAXN;

    // Kernel 0a/0b: weight folding (warp-parallel)
    {
        int warps = 8972;
        int blocks = (warps * 32 + 255) / 256;
        precompute_a<<<blocks, 256>>>(Wq, Wk, Wv, Wo, b0p, Bt);
        precompute_b<<<8, 256>>>(Wk);
    }
    // Kernel 1: x @ Wcomb + bias  ->  g_scr
    {
        dim3 grid((N + BM - 1) / BM, NCOL / BN);
        gemm_kernel<<<grid, 128>>>(x, N);
    }
    // Kernel 2: fused attention
    {
        int blocks = (N + 7) / 8;
        attn_kernel<<<blocks, 256>>>(ts, idx, w0p, b0p, Wt, Bt, bo, out, N);
    }
}

// round 8
// speedup vs baseline: 1.4225x; 1.2981x over previous
#include <cuda_runtime.h>
#include <math.h>

// ---------------------------------------------------------------------------
// TGAT fused kernel, restructured:
//   scratch  = x @ [Wq128 | Wk128 | Wv128@Wo | Wq128@Wk'^T] + [qc|0|0|qkc]
//            = [ Q | XK | XVO | QKp ]   (N x 448)
//   score_nk = (Q[n]·XK[j] + QKp[n]·te(t)) / sqrt(128)
//   out[n]   = relu( sum_k attn_k * XVO[j_k] + tebar @ (Wv'@Wo) + bo )
// ---------------------------------------------------------------------------

#define MAXN 50176
#define FEAT 128
#define T2V  64
#define KNBR 16
#define NCOL 448   // 128 Q + 128 XK + 128 XVO + 64 QKp

__device__ __align__(16) float g_scr[MAXN * NCOL];     // ~90 MB scratch
__device__ __align__(16) float g_Wcomb[FEAT * NCOL];   // combined GEMM weights
__device__ __align__(16) float g_bias[NCOL];
__device__ __align__(16) float g_Wvo[T2V * FEAT];      // Wv' @ Wo

// ---------------------------------------------------------------------------
// Kernel 0a: fold weights, warp-parallel & coalesced.
// ---------------------------------------------------------------------------
__global__ void __launch_bounds__(256) precompute_a(
        const float* __restrict__ Wq, const float* __restrict__ Wk,
        const float* __restrict__ Wv, const float* __restrict__ Wo,
        const float* __restrict__ b0p, const float* __restrict__ Bt) {
    int w    = (blockIdx.x * blockDim.x + threadIdx.x) >> 5;
    int lane = threadIdx.x & 31;

    if (w < 512) {                         // WvO128 [128 x 128]
        int f = w >> 2, c = ((w & 3) << 5) + lane;
        float acc = 0.f;
        #pragma unroll 8
        for (int h = 0; h < 128; h++)
            acc = fmaf(Wv[f * 128 + h], Wo[h * 128 + c], acc);
        g_Wcomb[f * NCOL + 256 + c] = acc;
    } else if (w < 768) {                  // Wvo [64 x 128]
        int j = (w - 512) >> 2, c = ((w & 3) << 5) + lane;
        float acc = 0.f;
        #pragma unroll 8
        for (int h = 0; h < 128; h++)
            acc = fmaf(Wv[(128 + j) * 128 + h], Wo[h * 128 + c], acc);
        g_Wvo[j * 128 + c] = acc;
    } else if (w < 768 + 8192) {           // Wqk [128 x 64] + copy Wq/Wk cols
        int e = w - 768;
        int f = e >> 6, j = e & 63;
        float acc = 0.f;
        #pragma unroll
        for (int i = 0; i < 4; i++) {
            int h = lane + i * 32;
            acc = fmaf(Wq[f * 128 + h], Wk[(128 + j) * 128 + h], acc);
        }
        #pragma unroll
        for (int off = 16; off; off >>= 1)
            acc += __shfl_xor_sync(0xffffffffu, acc, off);
        if (lane == 0) g_Wcomb[f * NCOL + 384 + j] = acc;
        // Copy plain Wq/Wk columns: c = j*2+lane spans [0,128) exactly.
        if (lane < 2) {
            int c = j * 2 + lane;
            g_Wcomb[f * NCOL + c]       = Wq[f * 128 + c];
            g_Wcomb[f * NCOL + 128 + c] = Wk[f * 128 + c];
        }
    } else if (w < 8964) {                 // qc [128]
        int c = ((w - 8960) << 5) + lane;
        float acc = b0p[0] * Wq[128 * 128 + c];
        for (int f = 1; f < T2V; f++)
            acc = fmaf(sinf(Bt[f - 1]), Wq[(128 + f) * 128 + c], acc);
        g_bias[c] = acc;
    } else if (w < 8972) {                 // zero bias cols [128,384)
        int c = 128 + ((w - 8964) << 5) + lane;
        g_bias[c] = 0.f;
    }
}

// ---------------------------------------------------------------------------
// Kernel 0b: qkc[j] = sum_h qc[h] * Wk[128+j][h]  (needs qc from 0a)
// ---------------------------------------------------------------------------
__global__ void precompute_b(const float* __restrict__ Wk) {
    int w    = (blockIdx.x * blockDim.x + threadIdx.x) >> 5;
    int lane = threadIdx.x & 31;
    if (w >= 64) return;
    float acc = 0.f;
    #pragma unroll
    for (int i = 0; i < 4; i++) {
        int h = lane + i * 32;
        acc = fmaf(g_bias[h], Wk[(128 + w) * 128 + h], acc);
    }
    #pragma unroll
    for (int off = 16; off; off >>= 1)
        acc += __shfl_xor_sync(0xffffffffu, acc, off);
    if (lane == 0) g_bias[384 + w] = acc;
}

// ---------------------------------------------------------------------------
// Kernel 1: fp32 SGEMM  scr[N,448] = x[N,128] @ Wcomb[128,448] + bias
// BM=128, BN=64, BK=32, 128 threads, 8x8 microtile.
// ---------------------------------------------------------------------------
#define BM 128
#define BN 64
#define BK 32

__global__ void __launch_bounds__(128) gemm_kernel(const float* __restrict__ x, int N) {
    __shared__ float As[BK][BM + 4];   // A transposed, padded
    __shared__ float Bs[BK][BN];

    int tid = threadIdx.x;
    int tx = tid & 7;    // N direction (8 * 8 = 64)
    int ty = tid >> 3;   // M direction (16 * 8 = 128)
    int row0 = blockIdx.x * BM;
    int c0   = blockIdx.y * BN;

    float acc[8][8];
    #pragma unroll
    for (int i = 0; i < 8; i++)
        #pragma unroll
        for (int j = 0; j < 8; j++) acc[i][j] = 0.f;

    for (int kk = 0; kk < FEAT; kk += BK) {
        #pragma unroll
        for (int i = 0; i < 8; i++) {
            int slot = tid + i * 128;
            int m  = slot >> 3;
            int k4 = (slot & 7) << 2;
            int r  = row0 + m;
            float4 a = (r < N) ? *(const float4*)(x + (size_t)r * FEAT + kk + k4)
                               : make_float4(0.f, 0.f, 0.f, 0.f);
            As[k4 + 0][m] = a.x;
            As[k4 + 1][m] = a.y;
            As[k4 + 2][m] = a.z;
            As[k4 + 3][m] = a.w;
        }
        #pragma unroll
        for (int i = 0; i < 4; i++) {
            int slot = tid + i * 128;
            int k  = slot >> 4;
            int c4 = (slot & 15) << 2;
            *(float4*)(&Bs[k][c4]) = *(const float4*)(g_Wcomb + (size_t)(kk + k) * NCOL + c0 + c4);
        }
        __syncthreads();

        #pragma unroll
        for (int k = 0; k < BK; k++) {
            float af[8], bf[8];
            *(float4*)(af)     = *(const float4*)(&As[k][ty * 8]);
            *(float4*)(af + 4) = *(const float4*)(&As[k][ty * 8 + 4]);
            *(float4*)(bf)     = *(const float4*)(&Bs[k][tx * 8]);
            *(float4*)(bf + 4) = *(const float4*)(&Bs[k][tx * 8 + 4]);
            #pragma unroll
            for (int i = 0; i < 8; i++)
                #pragma unroll
                for (int j = 0; j < 8; j++)
                    acc[i][j] = fmaf(af[i], bf[j], acc[i][j]);
        }
        __syncthreads();
    }

    float4 bias0 = *(const float4*)(g_bias + c0 + tx * 8);
    float4 bias1 = *(const float4*)(g_bias + c0 + tx * 8 + 4);
    #pragma unroll
    for (int i = 0; i < 8; i++) {
        int r = row0 + ty * 8 + i;
        if (r < N) {
            float4 o0, o1;
            o0.x = acc[i][0] + bias0.x;  o0.y = acc[i][1] + bias0.y;
            o0.z = acc[i][2] + bias0.z;  o0.w = acc[i][3] + bias0.w;
            o1.x = acc[i][4] + bias1.x;  o1.y = acc[i][5] + bias1.y;
            o1.z = acc[i][6] + bias1.z;  o1.w = acc[i][7] + bias1.w;
            *(float4*)(g_scr + (size_t)r * NCOL + c0 + tx * 8)     = o0;
            *(float4*)(g_scr + (size_t)r * NCOL + c0 + tx * 8 + 4) = o1;
        }
    }
}

// ---------------------------------------------------------------------------
// Kernel 2: fused attention. One warp per node, 8 warps (256 thr) per block.
// __sinf (MUFU) instead of libm sinf: |args| <~6 so abs err ~1e-6, and it
// removes the range-reduction register pressure. launch_bounds forces 64 regs
// -> 4 CTAs/SM -> ~50% occupancy (was 24% @ 99 regs).
// ---------------------------------------------------------------------------
__global__ void __launch_bounds__(256, 4) attn_kernel(
    const float* __restrict__ ts, const int* __restrict__ idx,
    const float* __restrict__ w0p, const float* __restrict__ b0p,
    const float* __restrict__ Wt,  const float* __restrict__ Bt,
    const float* __restrict__ bo,  float* __restrict__ out, int N) {

    __shared__ float te_s[8][KNBR * T2V];   // 32 KB

    const float* __restrict__ scr = g_scr;
    const float* __restrict__ wvo = g_Wvo;

    int warp = threadIdx.x >> 5;
    int lane = threadIdx.x & 31;
    int n = blockIdx.x * 8 + warp;
    if (n >= N) return;

    const float* scr_n = scr + (size_t)n * NCOL;
    float4 qv   = *(const float4*)(scr_n + lane * 4);
    float  qkp0 = scr_n[384 + lane];
    float  qkp1 = scr_n[384 + 32 + lane];

    float w0 = w0p[0], b0 = b0p[0];
    float W0 = (lane == 0) ? 0.f : Wt[lane - 1];
    float B0 = (lane == 0) ? 0.f : Bt[lane - 1];
    float W1 = Wt[lane + 31];
    float B1 = Bt[lane + 31];

    float* mte = te_s[warp];
    int   jj[KNBR];
    float s[KNBR];

    // Pass 1: te + scores
    #pragma unroll
    for (int k = 0; k < KNBR; k++) {
        float t = ts[(size_t)n * KNBR + k];
        int   j = idx[(size_t)n * KNBR + k];
        jj[k] = j;
        float v0 = (lane == 0) ? fmaf(t, w0, b0) : __sinf(fmaf(t, W0, B0));
        float v1 = __sinf(fmaf(t, W1, B1));
        mte[k * T2V + lane]      = v0;
        mte[k * T2V + 32 + lane] = v1;
        float4 kv = *(const float4*)(scr + (size_t)j * NCOL + 128 + lane * 4);
        float p = qv.x * kv.x + qv.y * kv.y + qv.z * kv.z + qv.w * kv.w
                + qkp0 * v0 + qkp1 * v1;
        #pragma unroll
        for (int off = 16; off; off >>= 1)
            p += __shfl_xor_sync(0xffffffffu, p, off);
        s[k] = p * 0.08838834764831845f;   // 1/sqrt(128)
    }

    // Softmax over 16 scores (replicated in every lane)
    float m = s[0];
    #pragma unroll
    for (int k = 1; k < KNBR; k++) m = fmaxf(m, s[k]);
    float wsum = 0.f;
    #pragma unroll
    for (int k = 0; k < KNBR; k++) { s[k] = __expf(s[k] - m); wsum += s[k]; }
    float inv = 1.f / wsum;

    // Pass 2: tebar + weighted XVO gather
    float4 acc = make_float4(0.f, 0.f, 0.f, 0.f);
    float tb0 = 0.f, tb1 = 0.f;
    #pragma unroll
    for (int k = 0; k < KNBR; k++) {
        float a = s[k] * inv;
        tb0 = fmaf(a, mte[k * T2V + lane], tb0);
        tb1 = fmaf(a, mte[k * T2V + 32 + lane], tb1);
        float4 vv = *(const float4*)(scr + (size_t)jj[k] * NCOL + 256 + lane * 4);
        acc.x = fmaf(a, vv.x, acc.x);
        acc.y = fmaf(a, vv.y, acc.y);
        acc.z = fmaf(a, vv.z, acc.z);
        acc.w = fmaf(a, vv.w, acc.w);
    }

    // Broadcast tebar through smem (reuse row 0 of this warp's te buffer)
    __syncwarp();
    mte[lane]      = tb0;
    mte[32 + lane] = tb1;
    __syncwarp();

    // acc += tebar @ Wvo  (Wvo is 32 KB -> L1/L2-resident)
    const float4* Wvo4 = (const float4*)wvo;
    #pragma unroll 8
    for (int f = 0; f < T2V; f++) {
        float tb = mte[f];
        float4 wv = __ldg(&Wvo4[f * 32 + lane]);
        acc.x = fmaf(tb, wv.x, acc.x);
        acc.y = fmaf(tb, wv.y, acc.y);
        acc.z = fmaf(tb, wv.z, acc.z);
        acc.w = fmaf(tb, wv.w, acc.w);
    }

    float4 bo4 = *(const float4*)(bo + lane * 4);
    float4 o;
    o.x = fmaxf(acc.x + bo4.x, 0.f);
    o.y = fmaxf(acc.y + bo4.y, 0.f);
    o.z = fmaxf(acc.z + bo4.z, 0.f);
    o.w = fmaxf(acc.w + bo4.w, 0.f);
    *(float4*)(out + (size_t)n * FEAT + lane * 4) = o;
}

// ---------------------------------------------------------------------------
extern "C" void kernel_launch(void* const* d_in, const int* in_sizes, int n_in,
                              void* d_out, int out_size) {
    const float* x    = (const float*)d_in[0];
    const float* ts   = (const float*)d_in[1];
    const int*   idx  = (const int*)  d_in[2];
    const float* w0p  = (const float*)d_in[3];
    const float* b0p  = (const float*)d_in[4];
    const float* Wt   = (const float*)d_in[5];
    const float* Bt   = (const float*)d_in[6];
    const float* Wq   = (const float*)d_in[7];
    const float* Wk   = (const float*)d_in[8];
    const float* Wv   = (const float*)d_in[9];
    const float* Wo   = (const float*)d_in[10];
    const float* bo   = (const float*)d_in[11];
    float* out = (float*)d_out;

    int N = in_sizes[0] / FEAT;
    if (N > MAXN) N = MAXN;

    // Kernel 0a/0b: weight folding (warp-parallel)
    {
        int warps = 8972;
        int blocks = (warps * 32 + 255) / 256;
        precompute_a<<<blocks, 256>>>(Wq, Wk, Wv, Wo, b0p, Bt);
        precompute_b<<<8, 256>>>(Wk);
    }
    // Kernel 1: x @ Wcomb + bias  ->  g_scr
    {
        dim3 grid((N + BM - 1) / BM, NCOL / BN);
        gemm_kernel<<<grid, 128>>>(x, N);
    }
    // Kernel 2: fused attention
    {
        int blocks = (N + 7) / 8;
        attn_kernel<<<blocks, 256>>>(ts, idx, w0p, b0p, Wt, Bt, bo, out, N);
    }
}

// round 11
// speedup vs baseline: 1.6715x; 1.1751x over previous
#include <cuda_runtime.h>
#include <math.h>

// ---------------------------------------------------------------------------
// TGAT fused kernel, restructured:
//   scratch  = x @ [Wq128 | Wk128 | Wv128@Wo | Wq128@Wk'^T] + [qc|0|0|qkc]
//            = [ Q | XK | XVO | QKp ]   (N x 448)
//   score_nk = (Q[n]·XK[j] + QKp[n]·te(t)) / sqrt(128)
//   attn:  online softmax -> out[n] = agg (partial), tebar[n] to scratch
//   epilogue: out[n] = relu(out[n] + tebar[n] @ (Wv'@Wo) + bo)
// ---------------------------------------------------------------------------

#define MAXN 50176
#define FEAT 128
#define T2V  64
#define KNBR 16
#define NCOL 448   // 128 Q + 128 XK + 128 XVO + 64 QKp
#define EROWS 64

__device__ __align__(16) float g_scr[MAXN * NCOL];     // ~90 MB scratch
__device__ __align__(16) float g_Wcomb[FEAT * NCOL];   // combined GEMM weights
__device__ __align__(16) float g_bias[NCOL];
__device__ __align__(16) float g_Wvo[T2V * FEAT];      // Wv' @ Wo
__device__ __align__(16) float g_tebar[MAXN * T2V];    // attn-weighted te

// ---------------------------------------------------------------------------
// Kernel 0a: fold weights, warp-parallel & coalesced.
// ---------------------------------------------------------------------------
__global__ void __launch_bounds__(256) precompute_a(
        const float* __restrict__ Wq, const float* __restrict__ Wk,
        const float* __restrict__ Wv, const float* __restrict__ Wo,
        const float* __restrict__ b0p, const float* __restrict__ Bt) {
    int w    = (blockIdx.x * blockDim.x + threadIdx.x) >> 5;
    int lane = threadIdx.x & 31;

    if (w < 512) {                         // WvO128 [128 x 128]
        int f = w >> 2, c = ((w & 3) << 5) + lane;
        float acc = 0.f;
        #pragma unroll 8
        for (int h = 0; h < 128; h++)
            acc = fmaf(Wv[f * 128 + h], Wo[h * 128 + c], acc);
        g_Wcomb[f * NCOL + 256 + c] = acc;
    } else if (w < 768) {                  // Wvo [64 x 128]
        int j = (w - 512) >> 2, c = ((w & 3) << 5) + lane;
        float acc = 0.f;
        #pragma unroll 8
        for (int h = 0; h < 128; h++)
            acc = fmaf(Wv[(128 + j) * 128 + h], Wo[h * 128 + c], acc);
        g_Wvo[j * 128 + c] = acc;
    } else if (w < 768 + 8192) {           // Wqk [128 x 64] + copy Wq/Wk cols
        int e = w - 768;
        int f = e >> 6, j = e & 63;
        float acc = 0.f;
        #pragma unroll
        for (int i = 0; i < 4; i++) {
            int h = lane + i * 32;
            acc = fmaf(Wq[f * 128 + h], Wk[(128 + j) * 128 + h], acc);
        }
        #pragma unroll
        for (int off = 16; off; off >>= 1)
            acc += __shfl_xor_sync(0xffffffffu, acc, off);
        if (lane == 0) g_Wcomb[f * NCOL + 384 + j] = acc;
        // Copy plain Wq/Wk columns: c = j*2+lane spans [0,128) exactly.
        if (lane < 2) {
            int c = j * 2 + lane;
            g_Wcomb[f * NCOL + c]       = Wq[f * 128 + c];
            g_Wcomb[f * NCOL + 128 + c] = Wk[f * 128 + c];
        }
    } else if (w < 8964) {                 // qc [128]
        int c = ((w - 8960) << 5) + lane;
        float acc = b0p[0] * Wq[128 * 128 + c];
        for (int f = 1; f < T2V; f++)
            acc = fmaf(sinf(Bt[f - 1]), Wq[(128 + f) * 128 + c], acc);
        g_bias[c] = acc;
    } else if (w < 8972) {                 // zero bias cols [128,384)
        int c = 128 + ((w - 8964) << 5) + lane;
        g_bias[c] = 0.f;
    }
}

// ---------------------------------------------------------------------------
// Kernel 0b: qkc[j] = sum_h qc[h] * Wk[128+j][h]  (needs qc from 0a)
// ---------------------------------------------------------------------------
__global__ void precompute_b(const float* __restrict__ Wk) {
    int w    = (blockIdx.x * blockDim.x + threadIdx.x) >> 5;
    int lane = threadIdx.x & 31;
    if (w >= 64) return;
    float acc = 0.f;
    #pragma unroll
    for (int i = 0; i < 4; i++) {
        int h = lane + i * 32;
        acc = fmaf(g_bias[h], Wk[(128 + w) * 128 + h], acc);
    }
    #pragma unroll
    for (int off = 16; off; off >>= 1)
        acc += __shfl_xor_sync(0xffffffffu, acc, off);
    if (lane == 0) g_bias[384 + w] = acc;
}

// ---------------------------------------------------------------------------
// Kernel 1: fp32 SGEMM  scr[N,448] = x[N,128] @ Wcomb[128,448] + bias
// BM=128, BN=64, BK=32, 128 threads, 8x8 microtile.
// ---------------------------------------------------------------------------
#define BM 128
#define BN 64
#define BK 32

__global__ void __launch_bounds__(128) gemm_kernel(const float* __restrict__ x, int N) {
    __shared__ float As[BK][BM + 4];   // A transposed, padded
    __shared__ float Bs[BK][BN];

    int tid = threadIdx.x;
    int tx = tid & 7;    // N direction (8 * 8 = 64)
    int ty = tid >> 3;   // M direction (16 * 8 = 128)
    int row0 = blockIdx.x * BM;
    int c0   = blockIdx.y * BN;

    float acc[8][8];
    #pragma unroll
    for (int i = 0; i < 8; i++)
        #pragma unroll
        for (int j = 0; j < 8; j++) acc[i][j] = 0.f;

    for (int kk = 0; kk < FEAT; kk += BK) {
        #pragma unroll
        for (int i = 0; i < 8; i++) {
            int slot = tid + i * 128;
            int m  = slot >> 3;
            int k4 = (slot & 7) << 2;
            int r  = row0 + m;
            float4 a = (r < N) ? *(const float4*)(x + (size_t)r * FEAT + kk + k4)
                               : make_float4(0.f, 0.f, 0.f, 0.f);
            As[k4 + 0][m] = a.x;
            As[k4 + 1][m] = a.y;
            As[k4 + 2][m] = a.z;
            As[k4 + 3][m] = a.w;
        }
        #pragma unroll
        for (int i = 0; i < 4; i++) {
            int slot = tid + i * 128;
            int k  = slot >> 4;
            int c4 = (slot & 15) << 2;
            *(float4*)(&Bs[k][c4]) = *(const float4*)(g_Wcomb + (size_t)(kk + k) * NCOL + c0 + c4);
        }
        __syncthreads();

        #pragma unroll
        for (int k = 0; k < BK; k++) {
            float af[8], bf[8];
            *(float4*)(af)     = *(const float4*)(&As[k][ty * 8]);
            *(float4*)(af + 4) = *(const float4*)(&As[k][ty * 8 + 4]);
            *(float4*)(bf)     = *(const float4*)(&Bs[k][tx * 8]);
            *(float4*)(bf + 4) = *(const float4*)(&Bs[k][tx * 8 + 4]);
            #pragma unroll
            for (int i = 0; i < 8; i++)
                #pragma unroll
                for (int j = 0; j < 8; j++)
                    acc[i][j] = fmaf(af[i], bf[j], acc[i][j]);
        }
        __syncthreads();
    }

    float4 bias0 = *(const float4*)(g_bias + c0 + tx * 8);
    float4 bias1 = *(const float4*)(g_bias + c0 + tx * 8 + 4);
    #pragma unroll
    for (int i = 0; i < 8; i++) {
        int r = row0 + ty * 8 + i;
        if (r < N) {
            float4 o0, o1;
            o0.x = acc[i][0] + bias0.x;  o0.y = acc[i][1] + bias0.y;
            o0.z = acc[i][2] + bias0.z;  o0.w = acc[i][3] + bias0.w;
            o1.x = acc[i][4] + bias1.x;  o1.y = acc[i][5] + bias1.y;
            o1.z = acc[i][6] + bias1.z;  o1.w = acc[i][7] + bias1.w;
            *(float4*)(g_scr + (size_t)r * NCOL + c0 + tx * 8)     = o0;
            *(float4*)(g_scr + (size_t)r * NCOL + c0 + tx * 8 + 4) = o1;
        }
    }
}

// ---------------------------------------------------------------------------
// Kernel 2: fused attention, online softmax, single pass, NO smem, NO Wvo.
// One warp per node, 8 warps per block. Writes partial agg -> out,
// attn-weighted te -> g_tebar.
// ---------------------------------------------------------------------------
__global__ void __launch_bounds__(256, 5) attn_kernel(
    const float* __restrict__ ts, const int* __restrict__ idx,
    const float* __restrict__ w0p, const float* __restrict__ b0p,
    const float* __restrict__ Wt,  const float* __restrict__ Bt,
    float* __restrict__ out, int N) {

    const float* __restrict__ scr = g_scr;

    int warp = threadIdx.x >> 5;
    int lane = threadIdx.x & 31;
    int n = blockIdx.x * 8 + warp;
    if (n >= N) return;

    const float* scr_n = scr + (size_t)n * NCOL;
    float4 qv   = *(const float4*)(scr_n + lane * 4);
    float  qkp0 = scr_n[384 + lane];
    float  qkp1 = scr_n[384 + 32 + lane];

    float w0 = w0p[0], b0 = b0p[0];
    float W0 = (lane == 0) ? 0.f : Wt[lane - 1];
    float B0 = (lane == 0) ? 0.f : Bt[lane - 1];
    float W1 = Wt[lane + 31];
    float B1 = Bt[lane + 31];

    // lanes 0-15 hold ts[k], lanes 16-31 hold idx[k]; broadcast via shfl
    float tval = 0.f;
    int   jval = 0;
    if (lane < 16) tval = ts[(size_t)n * KNBR + lane];
    else           jval = idx[(size_t)n * KNBR + (lane - 16)];

    float m = -1e30f, l = 0.f;
    float tb0 = 0.f, tb1 = 0.f;
    float4 acc = make_float4(0.f, 0.f, 0.f, 0.f);

    #pragma unroll
    for (int k = 0; k < KNBR; k++) {
        float t = __shfl_sync(0xffffffffu, tval, k);
        int   j = __shfl_sync(0xffffffffu, jval, 16 + k);

        float v0 = (lane == 0) ? fmaf(t, w0, b0) : __sinf(fmaf(t, W0, B0));
        float v1 = __sinf(fmaf(t, W1, B1));

        const float* sj = scr + (size_t)j * NCOL;
        float4 kv = *(const float4*)(sj + 128 + lane * 4);
        float4 vv = *(const float4*)(sj + 256 + lane * 4);

        float p = qv.x * kv.x + qv.y * kv.y + qv.z * kv.z + qv.w * kv.w
                + qkp0 * v0 + qkp1 * v1;
        #pragma unroll
        for (int off = 16; off; off >>= 1)
            p += __shfl_xor_sync(0xffffffffu, p, off);
        float s = p * 0.08838834764831845f;   // 1/sqrt(128)

        float mn   = fmaxf(m, s);
        float corr = __expf(m - mn);          // first iter: exp(-huge)=0
        float wgt  = __expf(s - mn);
        l   = l   * corr + wgt;
        tb0 = tb0 * corr + wgt * v0;
        tb1 = tb1 * corr + wgt * v1;
        acc.x = acc.x * corr + wgt * vv.x;
        acc.y = acc.y * corr + wgt * vv.y;
        acc.z = acc.z * corr + wgt * vv.z;
        acc.w = acc.w * corr + wgt * vv.w;
        m = mn;
    }

    float inv = 1.f / l;
    g_tebar[(size_t)n * T2V + lane]      = tb0 * inv;
    g_tebar[(size_t)n * T2V + 32 + lane] = tb1 * inv;

    float4 o;
    o.x = acc.x * inv;  o.y = acc.y * inv;
    o.z = acc.z * inv;  o.w = acc.w * inv;
    *(float4*)(out + (size_t)n * FEAT + lane * 4) = o;
}

// ---------------------------------------------------------------------------
// Kernel 3: epilogue  out = relu(out + tebar @ Wvo + bo)
// 64 rows / block, Wvo (32KB) + tebar tile (16KB) staged in smem.
// Each warp: 8 rows x (lane-owned 4 cols), 2048 FMA / thread.
// ---------------------------------------------------------------------------
__global__ void __launch_bounds__(256) epilogue_kernel(
        const float* __restrict__ bo, float* __restrict__ out, int N) {
    __shared__ float wv_s[T2V * FEAT];     // 32 KB
    __shared__ float tb_s[EROWS * T2V];    // 16 KB

    int tid = threadIdx.x;
    int r0  = blockIdx.x * EROWS;

    // stage Wvo: 8192 floats = 256 thr x 8 float4
    #pragma unroll
    for (int i = 0; i < 8; i++) {
        int o = (tid + i * 256) * 4;
        *(float4*)(wv_s + o) = *(const float4*)(g_Wvo + o);
    }
    // stage tebar tile: 4096 floats = 256 thr x 4 float4 (flat, rows contiguous)
    int nflt = (N - r0 < EROWS ? N - r0 : EROWS) * T2V;
    #pragma unroll
    for (int i = 0; i < 4; i++) {
        int o = (tid + i * 256) * 4;
        float4 v = (o < nflt) ? *(const float4*)(g_tebar + (size_t)r0 * T2V + o)
                              : make_float4(0.f, 0.f, 0.f, 0.f);
        *(float4*)(tb_s + o) = v;
    }
    __syncthreads();

    int warp = tid >> 5;
    int lane = tid & 31;
    int rb   = warp * 8;   // this warp's 8 rows within the tile

    float4 acc[8];
    #pragma unroll
    for (int r = 0; r < 8; r++) {
        int row = r0 + rb + r;
        acc[r] = (row < N) ? *(const float4*)(out + (size_t)row * FEAT + lane * 4)
                           : make_float4(0.f, 0.f, 0.f, 0.f);
    }

    #pragma unroll
    for (int f4 = 0; f4 < T2V; f4 += 4) {
        float4 wv0 = *(const float4*)(wv_s + (f4 + 0) * FEAT + lane * 4);
        float4 wv1 = *(const float4*)(wv_s + (f4 + 1) * FEAT + lane * 4);
        float4 wv2 = *(const float4*)(wv_s + (f4 + 2) * FEAT + lane * 4);
        float4 wv3 = *(const float4*)(wv_s + (f4 + 3) * FEAT + lane * 4);
        #pragma unroll
        for (int r = 0; r < 8; r++) {
            float4 tb = *(const float4*)(tb_s + (rb + r) * T2V + f4);
            acc[r].x = fmaf(tb.x, wv0.x, acc[r].x);
            acc[r].y = fmaf(tb.x, wv0.y, acc[r].y);
            acc[r].z = fmaf(tb.x, wv0.z, acc[r].z);
            acc[r].w = fmaf(tb.x, wv0.w, acc[r].w);
            acc[r].x = fmaf(tb.y, wv1.x, acc[r].x);
            acc[r].y = fmaf(tb.y, wv1.y, acc[r].y);
            acc[r].z = fmaf(tb.y, wv1.z, acc[r].z);
            acc[r].w = fmaf(tb.y, wv1.w, acc[r].w);
            acc[r].x = fmaf(tb.z, wv2.x, acc[r].x);
            acc[r].y = fmaf(tb.z, wv2.y, acc[r].y);
            acc[r].z = fmaf(tb.z, wv2.z, acc[r].z);
            acc[r].w = fmaf(tb.z, wv2.w, acc[r].w);
            acc[r].x = fmaf(tb.w, wv3.x, acc[r].x);
            acc[r].y = fmaf(tb.w, wv3.y, acc[r].y);
            acc[r].z = fmaf(tb.w, wv3.z, acc[r].z);
            acc[r].w = fmaf(tb.w, wv3.w, acc[r].w);
        }
    }

    float4 bo4 = *(const float4*)(bo + lane * 4);
    #pragma unroll
    for (int r = 0; r < 8; r++) {
        int row = r0 + rb + r;
        if (row < N) {
            float4 o;
            o.x = fmaxf(acc[r].x + bo4.x, 0.f);
            o.y = fmaxf(acc[r].y + bo4.y, 0.f);
            o.z = fmaxf(acc[r].z + bo4.z, 0.f);
            o.w = fmaxf(acc[r].w + bo4.w, 0.f);
            *(float4*)(out + (size_t)row * FEAT + lane * 4) = o;
        }
    }
}

// ---------------------------------------------------------------------------
extern "C" void kernel_launch(void* const* d_in, const int* in_sizes, int n_in,
                              void* d_out, int out_size) {
    const float* x    = (const float*)d_in[0];
    const float* ts   = (const float*)d_in[1];
    const int*   idx  = (const int*)  d_in[2];
    const float* w0p  = (const float*)d_in[3];
    const float* b0p  = (const float*)d_in[4];
    const float* Wt   = (const float*)d_in[5];
    const float* Bt   = (const float*)d_in[6];
    const float* Wq   = (const float*)d_in[7];
    const float* Wk   = (const float*)d_in[8];
    const float* Wv   = (const float*)d_in[9];
    const float* Wo   = (const float*)d_in[10];
    const float* bo   = (const float*)d_in[11];
    float* out = (float*)d_out;

    int N = in_sizes[0] / FEAT;
    if (N > MAXN) N = MAXN;

    // Kernel 0a/0b: weight folding (warp-parallel)
    {
        int warps = 8972;
        int blocks = (warps * 32 + 255) / 256;
        precompute_a<<<blocks, 256>>>(Wq, Wk, Wv, Wo, b0p, Bt);
        precompute_b<<<8, 256>>>(Wk);
    }
    // Kernel 1: x @ Wcomb + bias  ->  g_scr
    {
        dim3 grid((N + BM - 1) / BM, NCOL / BN);
        gemm_kernel<<<grid, 128>>>(x, N);
    }
    // Kernel 2: fused attention (online softmax)
    {
        int blocks = (N + 7) / 8;
        attn_kernel<<<blocks, 256>>>(ts, idx, w0p, b0p, Wt, Bt, out, N);
    }
    // Kernel 3: epilogue out = relu(out + tebar@Wvo + bo)
    {
        int blocks = (N + EROWS - 1) / EROWS;
        epilogue_kernel<<<blocks, 256>>>(bo, out, N);
    }
}

// round 12
// speedup vs baseline: 1.6732x; 1.0010x over previous
#include <cuda_runtime.h>
#include <math.h>

// ---------------------------------------------------------------------------
// TGAT fused kernel, restructured:
//   scratch  = x @ [Wq128 | Wk128 | Wv128@Wo | Wq128@Wk'^T] + [qc|0|0|qkc]
//            = [ Q | XK | XVO | QKp ]   (N x 448)
//   score_nk = (Q[n]·XK[j] + QKp[n]·te(t)) / sqrt(128)
//   attn:  online softmax -> out[n] = agg (partial), tebar[n] to scratch
//   epilogue: out[n] = relu(out[n] + tebar[n] @ (Wv'@Wo) + bo)
// ---------------------------------------------------------------------------

#define MAXN 50176
#define FEAT 128
#define T2V  64
#define KNBR 16
#define NCOL 448   // 128 Q + 128 XK + 128 XVO + 64 QKp
#define EROWS 64

__device__ __align__(16) float g_scr[MAXN * NCOL];     // ~90 MB scratch
__device__ __align__(16) float g_Wcomb[FEAT * NCOL];   // combined GEMM weights
__device__ __align__(16) float g_bias[NCOL];
__device__ __align__(16) float g_Wvo[T2V * FEAT];      // Wv' @ Wo
__device__ __align__(16) float g_tebar[MAXN * T2V];    // attn-weighted te

// ---------------------------------------------------------------------------
// Kernel 0a: fold weights, warp-parallel & coalesced.
// ---------------------------------------------------------------------------
__global__ void __launch_bounds__(256) precompute_a(
        const float* __restrict__ Wq, const float* __restrict__ Wk,
        const float* __restrict__ Wv, const float* __restrict__ Wo,
        const float* __restrict__ b0p, const float* __restrict__ Bt) {
    int w    = (blockIdx.x * blockDim.x + threadIdx.x) >> 5;
    int lane = threadIdx.x & 31;

    if (w < 512) {                         // WvO128 [128 x 128]
        int f = w >> 2, c = ((w & 3) << 5) + lane;
        float acc = 0.f;
        #pragma unroll 8
        for (int h = 0; h < 128; h++)
            acc = fmaf(Wv[f * 128 + h], Wo[h * 128 + c], acc);
        g_Wcomb[f * NCOL + 256 + c] = acc;
    } else if (w < 768) {                  // Wvo [64 x 128]
        int j = (w - 512) >> 2, c = ((w & 3) << 5) + lane;
        float acc = 0.f;
        #pragma unroll 8
        for (int h = 0; h < 128; h++)
            acc = fmaf(Wv[(128 + j) * 128 + h], Wo[h * 128 + c], acc);
        g_Wvo[j * 128 + c] = acc;
    } else if (w < 768 + 8192) {           // Wqk [128 x 64] + copy Wq/Wk cols
        int e = w - 768;
        int f = e >> 6, j = e & 63;
        float acc = 0.f;
        #pragma unroll
        for (int i = 0; i < 4; i++) {
            int h = lane + i * 32;
            acc = fmaf(Wq[f * 128 + h], Wk[(128 + j) * 128 + h], acc);
        }
        #pragma unroll
        for (int off = 16; off; off >>= 1)
            acc += __shfl_xor_sync(0xffffffffu, acc, off);
        if (lane == 0) g_Wcomb[f * NCOL + 384 + j] = acc;
        // Copy plain Wq/Wk columns: c = j*2+lane spans [0,128) exactly.
        if (lane < 2) {
            int c = j * 2 + lane;
            g_Wcomb[f * NCOL + c]       = Wq[f * 128 + c];
            g_Wcomb[f * NCOL + 128 + c] = Wk[f * 128 + c];
        }
    } else if (w < 8964) {                 // qc [128]
        int c = ((w - 8960) << 5) + lane;
        float acc = b0p[0] * Wq[128 * 128 + c];
        for (int f = 1; f < T2V; f++)
            acc = fmaf(sinf(Bt[f - 1]), Wq[(128 + f) * 128 + c], acc);
        g_bias[c] = acc;
    } else if (w < 8972) {                 // zero bias cols [128,384)
        int c = 128 + ((w - 8964) << 5) + lane;
        g_bias[c] = 0.f;
    }
}

// ---------------------------------------------------------------------------
// Kernel 0b: qkc[j] = sum_h qc[h] * Wk[128+j][h]  (needs qc from 0a)
// ---------------------------------------------------------------------------
__global__ void precompute_b(const float* __restrict__ Wk) {
    int w    = (blockIdx.x * blockDim.x + threadIdx.x) >> 5;
    int lane = threadIdx.x & 31;
    if (w >= 64) return;
    float acc = 0.f;
    #pragma unroll
    for (int i = 0; i < 4; i++) {
        int h = lane + i * 32;
        acc = fmaf(g_bias[h], Wk[(128 + w) * 128 + h], acc);
    }
    #pragma unroll
    for (int off = 16; off; off >>= 1)
        acc += __shfl_xor_sync(0xffffffffu, acc, off);
    if (lane == 0) g_bias[384 + w] = acc;
}

// ---------------------------------------------------------------------------
// Kernel 1: fp32 SGEMM  scr[N,448] = x[N,128] @ Wcomb[128,448] + bias
// BM=128, BN=64, BK=32, 128 threads, 8x8 microtile.
// ---------------------------------------------------------------------------
#define BM 128
#define BN 64
#define BK 32

__global__ void __launch_bounds__(128) gemm_kernel(const float* __restrict__ x, int N) {
    __shared__ float As[BK][BM + 4];   // A transposed, padded
    __shared__ float Bs[BK][BN];

    int tid = threadIdx.x;
    int tx = tid & 7;    // N direction (8 * 8 = 64)
    int ty = tid >> 3;   // M direction (16 * 8 = 128)
    int row0 = blockIdx.x * BM;
    int c0   = blockIdx.y * BN;

    float acc[8][8];
    #pragma unroll
    for (int i = 0; i < 8; i++)
        #pragma unroll
        for (int j = 0; j < 8; j++) acc[i][j] = 0.f;

    for (int kk = 0; kk < FEAT; kk += BK) {
        #pragma unroll
        for (int i = 0; i < 8; i++) {
            int slot = tid + i * 128;
            int m  = slot >> 3;
            int k4 = (slot & 7) << 2;
            int r  = row0 + m;
            float4 a = (r < N) ? *(const float4*)(x + (size_t)r * FEAT + kk + k4)
                               : make_float4(0.f, 0.f, 0.f, 0.f);
            As[k4 + 0][m] = a.x;
            As[k4 + 1][m] = a.y;
            As[k4 + 2][m] = a.z;
            As[k4 + 3][m] = a.w;
        }
        #pragma unroll
        for (int i = 0; i < 4; i++) {
            int slot = tid + i * 128;
            int k  = slot >> 4;
            int c4 = (slot & 15) << 2;
            *(float4*)(&Bs[k][c4]) = *(const float4*)(g_Wcomb + (size_t)(kk + k) * NCOL + c0 + c4);
        }
        __syncthreads();

        #pragma unroll
        for (int k = 0; k < BK; k++) {
            float af[8], bf[8];
            *(float4*)(af)     = *(const float4*)(&As[k][ty * 8]);
            *(float4*)(af + 4) = *(const float4*)(&As[k][ty * 8 + 4]);
            *(float4*)(bf)     = *(const float4*)(&Bs[k][tx * 8]);
            *(float4*)(bf + 4) = *(const float4*)(&Bs[k][tx * 8 + 4]);
            #pragma unroll
            for (int i = 0; i < 8; i++)
                #pragma unroll
                for (int j = 0; j < 8; j++)
                    acc[i][j] = fmaf(af[i], bf[j], acc[i][j]);
        }
        __syncthreads();
    }

    float4 bias0 = *(const float4*)(g_bias + c0 + tx * 8);
    float4 bias1 = *(const float4*)(g_bias + c0 + tx * 8 + 4);
    #pragma unroll
    for (int i = 0; i < 8; i++) {
        int r = row0 + ty * 8 + i;
        if (r < N) {
            float4 o0, o1;
            o0.x = acc[i][0] + bias0.x;  o0.y = acc[i][1] + bias0.y;
            o0.z = acc[i][2] + bias0.z;  o0.w = acc[i][3] + bias0.w;
            o1.x = acc[i][4] + bias1.x;  o1.y = acc[i][5] + bias1.y;
            o1.z = acc[i][6] + bias1.z;  o1.w = acc[i][7] + bias1.w;
            *(float4*)(g_scr + (size_t)r * NCOL + c0 + tx * 8)     = o0;
            *(float4*)(g_scr + (size_t)r * NCOL + c0 + tx * 8 + 4) = o1;
        }
    }
}

// ---------------------------------------------------------------------------
// Kernel 2: fused attention, online softmax, single pass, NO smem, NO Wvo.
// One warp per node, 8 warps per block. Writes partial agg -> out,
// attn-weighted te -> g_tebar.
// ---------------------------------------------------------------------------
__global__ void __launch_bounds__(256, 5) attn_kernel(
    const float* __restrict__ ts, const int* __restrict__ idx,
    const float* __restrict__ w0p, const float* __restrict__ b0p,
    const float* __restrict__ Wt,  const float* __restrict__ Bt,
    float* __restrict__ out, int N) {

    const float* __restrict__ scr = g_scr;

    int warp = threadIdx.x >> 5;
    int lane = threadIdx.x & 31;
    int n = blockIdx.x * 8 + warp;
    if (n >= N) return;

    const float* scr_n = scr + (size_t)n * NCOL;
    float4 qv   = *(const float4*)(scr_n + lane * 4);
    float  qkp0 = scr_n[384 + lane];
    float  qkp1 = scr_n[384 + 32 + lane];

    float w0 = w0p[0], b0 = b0p[0];
    float W0 = (lane == 0) ? 0.f : Wt[lane - 1];
    float B0 = (lane == 0) ? 0.f : Bt[lane - 1];
    float W1 = Wt[lane + 31];
    float B1 = Bt[lane + 31];

    // lanes 0-15 hold ts[k], lanes 16-31 hold idx[k]; broadcast via shfl
    float tval = 0.f;
    int   jval = 0;
    if (lane < 16) tval = ts[(size_t)n * KNBR + lane];
    else           jval = idx[(size_t)n * KNBR + (lane - 16)];

    float m = -1e30f, l = 0.f;
    float tb0 = 0.f, tb1 = 0.f;
    float4 acc = make_float4(0.f, 0.f, 0.f, 0.f);

    #pragma unroll
    for (int k = 0; k < KNBR; k++) {
        float t = __shfl_sync(0xffffffffu, tval, k);
        int   j = __shfl_sync(0xffffffffu, jval, 16 + k);

        float v0 = (lane == 0) ? fmaf(t, w0, b0) : __sinf(fmaf(t, W0, B0));
        float v1 = __sinf(fmaf(t, W1, B1));

        const float* sj = scr + (size_t)j * NCOL;
        float4 kv = *(const float4*)(sj + 128 + lane * 4);
        float4 vv = *(const float4*)(sj + 256 + lane * 4);

        float p = qv.x * kv.x + qv.y * kv.y + qv.z * kv.z + qv.w * kv.w
                + qkp0 * v0 + qkp1 * v1;
        #pragma unroll
        for (int off = 16; off; off >>= 1)
            p += __shfl_xor_sync(0xffffffffu, p, off);
        float s = p * 0.08838834764831845f;   // 1/sqrt(128)

        float mn   = fmaxf(m, s);
        float corr = __expf(m - mn);          // first iter: exp(-huge)=0
        float wgt  = __expf(s - mn);
        l   = l   * corr + wgt;
        tb0 = tb0 * corr + wgt * v0;
        tb1 = tb1 * corr + wgt * v1;
        acc.x = acc.x * corr + wgt * vv.x;
        acc.y = acc.y * corr + wgt * vv.y;
        acc.z = acc.z * corr + wgt * vv.z;
        acc.w = acc.w * corr + wgt * vv.w;
        m = mn;
    }

    float inv = 1.f / l;
    g_tebar[(size_t)n * T2V + lane]      = tb0 * inv;
    g_tebar[(size_t)n * T2V + 32 + lane] = tb1 * inv;

    float4 o;
    o.x = acc.x * inv;  o.y = acc.y * inv;
    o.z = acc.z * inv;  o.w = acc.w * inv;
    *(float4*)(out + (size_t)n * FEAT + lane * 4) = o;
}

// ---------------------------------------------------------------------------
// Kernel 3: epilogue  out = relu(out + tebar @ Wvo + bo)
// 64 rows / block, Wvo (32KB) + tebar tile (16KB) staged in smem.
// Each warp: 8 rows x (lane-owned 4 cols), 2048 FMA / thread.
// ---------------------------------------------------------------------------
__global__ void __launch_bounds__(256) epilogue_kernel(
        const float* __restrict__ bo, float* __restrict__ out, int N) {
    __shared__ float wv_s[T2V * FEAT];     // 32 KB
    __shared__ float tb_s[EROWS * T2V];    // 16 KB

    int tid = threadIdx.x;
    int r0  = blockIdx.x * EROWS;

    // stage Wvo: 8192 floats = 256 thr x 8 float4
    #pragma unroll
    for (int i = 0; i < 8; i++) {
        int o = (tid + i * 256) * 4;
        *(float4*)(wv_s + o) = *(const float4*)(g_Wvo + o);
    }
    // stage tebar tile: 4096 floats = 256 thr x 4 float4 (flat, rows contiguous)
    int nflt = (N - r0 < EROWS ? N - r0 : EROWS) * T2V;
    #pragma unroll
    for (int i = 0; i < 4; i++) {
        int o = (tid + i * 256) * 4;
        float4 v = (o < nflt) ? *(const float4*)(g_tebar + (size_t)r0 * T2V + o)
                              : make_float4(0.f, 0.f, 0.f, 0.f);
        *(float4*)(tb_s + o) = v;
    }
    __syncthreads();

    int warp = tid >> 5;
    int lane = tid & 31;
    int rb   = warp * 8;   // this warp's 8 rows within the tile

    float4 acc[8];
    #pragma unroll
    for (int r = 0; r < 8; r++) {
        int row = r0 + rb + r;
        acc[r] = (row < N) ? *(const float4*)(out + (size_t)row * FEAT + lane * 4)
                           : make_float4(0.f, 0.f, 0.f, 0.f);
    }

    #pragma unroll
    for (int f4 = 0; f4 < T2V; f4 += 4) {
        float4 wv0 = *(const float4*)(wv_s + (f4 + 0) * FEAT + lane * 4);
        float4 wv1 = *(const float4*)(wv_s + (f4 + 1) * FEAT + lane * 4);
        float4 wv2 = *(const float4*)(wv_s + (f4 + 2) * FEAT + lane * 4);
        float4 wv3 = *(const float4*)(wv_s + (f4 + 3) * FEAT + lane * 4);
        #pragma unroll
        for (int r = 0; r < 8; r++) {
            float4 tb = *(const float4*)(tb_s + (rb + r) * T2V + f4);
            acc[r].x = fmaf(tb.x, wv0.x, acc[r].x);
            acc[r].y = fmaf(tb.x, wv0.y, acc[r].y);
            acc[r].z = fmaf(tb.x, wv0.z, acc[r].z);
            acc[r].w = fmaf(tb.x, wv0.w, acc[r].w);
            acc[r].x = fmaf(tb.y, wv1.x, acc[r].x);
            acc[r].y = fmaf(tb.y, wv1.y, acc[r].y);
            acc[r].z = fmaf(tb.y, wv1.z, acc[r].z);
            acc[r].w = fmaf(tb.y, wv1.w, acc[r].w);
            acc[r].x = fmaf(tb.z, wv2.x, acc[r].x);
            acc[r].y = fmaf(tb.z, wv2.y, acc[r].y);
            acc[r].z = fmaf(tb.z, wv2.z, acc[r].z);
            acc[r].w = fmaf(tb.z, wv2.w, acc[r].w);
            acc[r].x = fmaf(tb.w, wv3.x, acc[r].x);
            acc[r].y = fmaf(tb.w, wv3.y, acc[r].y);
            acc[r].z = fmaf(tb.w, wv3.z, acc[r].z);
            acc[r].w = fmaf(tb.w, wv3.w, acc[r].w);
        }
    }

    float4 bo4 = *(const float4*)(bo + lane * 4);
    #pragma unroll
    for (int r = 0; r < 8; r++) {
        int row = r0 + rb + r;
        if (row < N) {
            float4 o;
            o.x = fmaxf(acc[r].x + bo4.x, 0.f);
            o.y = fmaxf(acc[r].y + bo4.y, 0.f);
            o.z = fmaxf(acc[r].z + bo4.z, 0.f);
            o.w = fmaxf(acc[r].w + bo4.w, 0.f);
            *(float4*)(out + (size_t)row * FEAT + lane * 4) = o;
        }
    }
}

// ---------------------------------------------------------------------------
extern "C" void kernel_launch(void* const* d_in, const int* in_sizes, int n_in,
                              void* d_out, int out_size) {
    const float* x    = (const float*)d_in[0];
    const float* ts   = (const float*)d_in[1];
    const int*   idx  = (const int*)  d_in[2];
    const float* w0p  = (const float*)d_in[3];
    const float* b0p  = (const float*)d_in[4];
    const float* Wt   = (const float*)d_in[5];
    const float* Bt   = (const float*)d_in[6];
    const float* Wq   = (const float*)d_in[7];
    const float* Wk   = (const float*)d_in[8];
    const float* Wv   = (const float*)d_in[9];
    const float* Wo   = (const float*)d_in[10];
    const float* bo   = (const float*)d_in[11];
    float* out = (float*)d_out;

    int N = in_sizes[0] / FEAT;
    if (N > MAXN) N = MAXN;

    // Kernel 0a/0b: weight folding (warp-parallel)
    {
        int warps = 8972;
        int blocks = (warps * 32 + 255) / 256;
        precompute_a<<<blocks, 256>>>(Wq, Wk, Wv, Wo, b0p, Bt);
        precompute_b<<<8, 256>>>(Wk);
    }
    // Kernel 1: x @ Wcomb + bias  ->  g_scr
    {
        dim3 grid((N + BM - 1) / BM, NCOL / BN);
        gemm_kernel<<<grid, 128>>>(x, N);
    }
    // Kernel 2: fused attention (online softmax)
    {
        int blocks = (N + 7) / 8;
        attn_kernel<<<blocks, 256>>>(ts, idx, w0p, b0p, Wt, Bt, out, N);
    }
    // Kernel 3: epilogue out = relu(out + tebar@Wvo + bo)
    {
        int blocks = (N + EROWS - 1) / EROWS;
        epilogue_kernel<<<blocks, 256>>>(bo, out, N);
    }
}